// round 10
// baseline (speedup 1.0000x reference)
#include <cuda_runtime.h>
#include <math.h>
#include <stdint.h>

#define BB 2
#define SS 2048
#define DD 2304
#define NHQ 8
#define NHKV 4
#define HD 256
#define FF 9216
#define MM (BB*SS)   // 4096 rows

// ---------------- persistent scratch (no allocations allowed) ----------------
__device__ float g_x  [MM*DD];
__device__ float g_h  [MM*DD];
__device__ float g_q  [MM*NHQ*HD];
__device__ float g_k  [MM*NHKV*HD];
__device__ float g_v  [MM*NHKV*HD];
__device__ float g_att[MM*NHQ*HD];
__device__ float g_tmp[MM*DD];
__device__ float g_ff [MM*FF];

// ---------------- small helpers ----------------
__global__ void copy_kernel(float* __restrict__ dst, const float* __restrict__ src, int n) {
    int i = blockIdx.x * blockDim.x + threadIdx.x;
    if (i < n) dst[i] = src[i];
}

// out[row] = in[row] * rsqrt(mean(in^2)+eps) * scale
__global__ void rms_kernel(const float* __restrict__ in, const float* __restrict__ scale,
                           float* __restrict__ out) {
    int row = blockIdx.x;
    const float* r = in + (size_t)row * DD;
    float ss = 0.f;
    for (int i = threadIdx.x; i < DD; i += 256) { float v = r[i]; ss += v * v; }
    #pragma unroll
    for (int o = 16; o; o >>= 1) ss += __shfl_xor_sync(0xffffffffu, ss, o);
    __shared__ float red[8];
    if ((threadIdx.x & 31) == 0) red[threadIdx.x >> 5] = ss;
    __syncthreads();
    float tot = red[0]+red[1]+red[2]+red[3]+red[4]+red[5]+red[6]+red[7];
    float rs = rsqrtf(tot / (float)DD + 1e-6f);
    float* o = out + (size_t)row * DD;
    for (int i = threadIdx.x; i < DD; i += 256) o[i] = r[i] * rs * scale[i];
}

// x[row] += rms(a[row]) * scale
__global__ void rms_add_kernel(const float* __restrict__ a, const float* __restrict__ scale,
                               float* __restrict__ x) {
    int row = blockIdx.x;
    const float* r = a + (size_t)row * DD;
    float ss = 0.f;
    for (int i = threadIdx.x; i < DD; i += 256) { float v = r[i]; ss += v * v; }
    #pragma unroll
    for (int o = 16; o; o >>= 1) ss += __shfl_xor_sync(0xffffffffu, ss, o);
    __shared__ float red[8];
    if ((threadIdx.x & 31) == 0) red[threadIdx.x >> 5] = ss;
    __syncthreads();
    float tot = red[0]+red[1]+red[2]+red[3]+red[4]+red[5]+red[6]+red[7];
    float rs = rsqrtf(tot / (float)DD + 1e-6f);
    float* xo = x + (size_t)row * DD;
    for (int i = threadIdx.x; i < DD; i += 256) xo[i] += r[i] * rs * scale[i];
}

// ---------------- SGEMM: C = alpha * A[M,K] @ B[K,N]  (all dims multiples of tile) ----------------
// 128x128 tile, BK=8, 256 threads, 8x8 per thread.
__global__ void __launch_bounds__(256) sgemm_kernel(const float* __restrict__ A,
                                                    const float* __restrict__ B,
                                                    float* __restrict__ C,
                                                    int M, int N, int K, float alpha) {
    __shared__ float As[8][128];
    __shared__ float Bs[8][128];
    int tid = threadIdx.x;
    int bx = blockIdx.x, by = blockIdx.y;
    int tx = tid & 15, ty = tid >> 4;

    const float* Ap = A + (size_t)(by * 128) * K;
    const float* Bp = B + bx * 128;

    int arow = tid >> 1;              // 0..127
    int acol = (tid & 1) * 4;         // 0 or 4
    int brow = tid >> 5;              // 0..7
    int bcol = (tid & 31) * 4;        // 0..124

    float acc[8][8];
    #pragma unroll
    for (int i = 0; i < 8; i++)
        #pragma unroll
        for (int j = 0; j < 8; j++) acc[i][j] = 0.f;

    for (int k0 = 0; k0 < K; k0 += 8) {
        float4 av = *(const float4*)(Ap + (size_t)arow * K + k0 + acol);
        As[acol + 0][arow] = av.x;
        As[acol + 1][arow] = av.y;
        As[acol + 2][arow] = av.z;
        As[acol + 3][arow] = av.w;
        float4 bv = *(const float4*)(Bp + (size_t)(k0 + brow) * N + bcol);
        *(float4*)&Bs[brow][bcol] = bv;
        __syncthreads();
        #pragma unroll
        for (int kk = 0; kk < 8; kk++) {
            float ar[8], br[8];
            *(float4*)&ar[0] = *(const float4*)&As[kk][ty * 8];
            *(float4*)&ar[4] = *(const float4*)&As[kk][ty * 8 + 4];
            *(float4*)&br[0] = *(const float4*)&Bs[kk][tx * 8];
            *(float4*)&br[4] = *(const float4*)&Bs[kk][tx * 8 + 4];
            #pragma unroll
            for (int i = 0; i < 8; i++)
                #pragma unroll
                for (int j = 0; j < 8; j++) acc[i][j] += ar[i] * br[j];
        }
        __syncthreads();
    }

    #pragma unroll
    for (int i = 0; i < 8; i++) {
        int row = by * 128 + ty * 8 + i;
        float* Cp = C + (size_t)row * N + bx * 128 + tx * 8;
        float4 o0 = make_float4(alpha*acc[i][0], alpha*acc[i][1], alpha*acc[i][2], alpha*acc[i][3]);
        float4 o1 = make_float4(alpha*acc[i][4], alpha*acc[i][5], alpha*acc[i][6], alpha*acc[i][7]);
        *(float4*)(Cp)     = o0;
        *(float4*)(Cp + 4) = o1;
    }
}

__device__ __forceinline__ float gelu_tanh(float x) {
    float x3 = x * x * x;
    return 0.5f * x * (1.f + tanhf(0.7978845608028654f * (x + 0.044715f * x3)));
}

// Fused GeGLU: C[M,N] = gelu(A@W0) * (A@W1).  128x64 tile, BK=8, 256 threads, 8x4 per thread.
__global__ void __launch_bounds__(256) ffw_dual_kernel(const float* __restrict__ A,
                                                       const float* __restrict__ W0,
                                                       const float* __restrict__ W1,
                                                       float* __restrict__ C,
                                                       int M, int N, int K) {
    __shared__ float As[8][128];
    __shared__ float B0s[8][64];
    __shared__ float B1s[8][64];
    int tid = threadIdx.x;
    int bx = blockIdx.x, by = blockIdx.y;
    int tx = tid & 15, ty = tid >> 4;

    const float* Ap  = A  + (size_t)(by * 128) * K;
    const float* B0p = W0 + bx * 64;
    const float* B1p = W1 + bx * 64;

    int arow = tid >> 1;
    int acol = (tid & 1) * 4;
    int brow = tid >> 5;              // 0..7
    int bcol = (tid & 31) * 2;        // 0..62

    float acc0[8][4], acc1[8][4];
    #pragma unroll
    for (int i = 0; i < 8; i++)
        #pragma unroll
        for (int j = 0; j < 4; j++) { acc0[i][j] = 0.f; acc1[i][j] = 0.f; }

    for (int k0 = 0; k0 < K; k0 += 8) {
        float4 av = *(const float4*)(Ap + (size_t)arow * K + k0 + acol);
        As[acol + 0][arow] = av.x;
        As[acol + 1][arow] = av.y;
        As[acol + 2][arow] = av.z;
        As[acol + 3][arow] = av.w;
        float2 b0 = *(const float2*)(B0p + (size_t)(k0 + brow) * N + bcol);
        float2 b1 = *(const float2*)(B1p + (size_t)(k0 + brow) * N + bcol);
        *(float2*)&B0s[brow][bcol] = b0;
        *(float2*)&B1s[brow][bcol] = b1;
        __syncthreads();
        #pragma unroll
        for (int kk = 0; kk < 8; kk++) {
            float ar[8], br0[4], br1[4];
            *(float4*)&ar[0] = *(const float4*)&As[kk][ty * 8];
            *(float4*)&ar[4] = *(const float4*)&As[kk][ty * 8 + 4];
            *(float4*)&br0[0] = *(const float4*)&B0s[kk][tx * 4];
            *(float4*)&br1[0] = *(const float4*)&B1s[kk][tx * 4];
            #pragma unroll
            for (int i = 0; i < 8; i++)
                #pragma unroll
                for (int j = 0; j < 4; j++) {
                    acc0[i][j] += ar[i] * br0[j];
                    acc1[i][j] += ar[i] * br1[j];
                }
        }
        __syncthreads();
    }

    #pragma unroll
    for (int i = 0; i < 8; i++) {
        int row = by * 128 + ty * 8 + i;
        float* Cp = C + (size_t)row * N + bx * 64 + tx * 4;
        #pragma unroll
        for (int j = 0; j < 4; j++) Cp[j] = gelu_tanh(acc0[i][j]) * acc1[i][j];
    }
}

// ---------------- RoPE (in-place), half = 128 ----------------
__global__ void rope_kernel(float* __restrict__ x, const int* __restrict__ positions, int H, int total) {
    int idx = blockIdx.x * blockDim.x + threadIdx.x;
    if (idx >= total) return;
    int i = idx & 127;
    int h = (idx >> 7) % H;
    int s = (idx / (128 * H)) % SS;
    int b = idx / (128 * H * SS);
    int p = positions[b * SS + s];
    double f = exp2(-(double)i * (13.287712379549449 / 128.0)); // log2(10000)=13.2877...
    double ang = (double)p * f;
    double sd, cd;
    sincos(ang, &sd, &cd);
    float sn = (float)sd, cs = (float)cd;
    size_t base = ((size_t)(b * SS + s) * H + h) * HD;
    float x1 = x[base + i], x2 = x[base + 128 + i];
    x[base + i]       = x1 * cs - x2 * sn;
    x[base + 128 + i] = x2 * cs + x1 * sn;
}

// ---------------- attention: online softmax, softcap, causal+window+segment ----------------
// grid: (S/32, HQ, B); block 256 = 8 warps; warp handles 4 queries; lane owns one key per 32-key tile.
#define KPAD 257
#define ATTN_SMEM_FLOATS (32*256 + 32*KPAD + 32*KPAD + 8*4*32 + 64)
#define ATTN_SMEM_BYTES (ATTN_SMEM_FLOATS * 4)

__global__ void __launch_bounds__(256) attn_kernel(const float* __restrict__ q,
                                                   const float* __restrict__ k,
                                                   const float* __restrict__ v,
                                                   const int* __restrict__ pos,
                                                   const int* __restrict__ seg,
                                                   float* __restrict__ out,
                                                   int window) {
    extern __shared__ float sm[];
    float* Qs = sm;                     // [32][256]
    float* Ks = Qs + 32 * 256;          // [32][257]
    float* Vs = Ks + 32 * KPAD;         // [32][257]
    float* Ps = Vs + 32 * KPAD;         // [8 warps][4][32]
    int* kposs = (int*)(Ps + 8 * 4 * 32);
    int* ksegs = kposs + 32;

    int b = blockIdx.z, h = blockIdx.y, qt = blockIdx.x;
    int kvh = h / (NHQ / NHKV);
    int tid = threadIdx.x, w = tid >> 5, lane = tid & 31;
    int q0g = qt * 32;

    for (int t = tid; t < 32 * 256; t += 256) {
        int lq = t >> 8, d = t & 255;
        Qs[t] = q[((size_t)(b * SS + q0g + lq) * NHQ + h) * HD + d];
    }

    int qp[4], qsg[4];
    #pragma unroll
    for (int qi = 0; qi < 4; qi++) {
        int qg = q0g + w * 4 + qi;
        qp[qi]  = pos[b * SS + qg];
        qsg[qi] = seg[b * SS + qg];
    }

    float mval[4], lval[4], acc[4][8];
    #pragma unroll
    for (int qi = 0; qi < 4; qi++) {
        mval[qi] = -1e30f; lval[qi] = 0.f;
        #pragma unroll
        for (int t = 0; t < 8; t++) acc[qi][t] = 0.f;
    }

    int kend = q0g + 32;
    int kstart = 0;
    { int lo = q0g - (window - 1); if (lo > 0) kstart = lo & ~31; }

    for (int kb = kstart; kb < kend; kb += 32) {
        __syncthreads();
        for (int t = tid; t < 32 * 256; t += 256) {
            int kk = t >> 8, d = t & 255;
            size_t gi = ((size_t)(b * SS + kb + kk) * NHKV + kvh) * HD + d;
            Ks[kk * KPAD + d] = k[gi];
            Vs[kk * KPAD + d] = v[gi];
        }
        if (tid < 32) { kposs[tid] = pos[b * SS + kb + tid]; ksegs[tid] = seg[b * SS + kb + tid]; }
        __syncthreads();

        int kp = kposs[lane], ks = ksegs[lane];
        const float* kr = Ks + lane * KPAD;
        const float* qr = Qs + (w * 4) * 256;
        float dot[4] = {0.f, 0.f, 0.f, 0.f};
        #pragma unroll 8
        for (int d = 0; d < 256; d++) {
            float kvv = kr[d];
            dot[0] += qr[d]       * kvv;
            dot[1] += qr[256 + d] * kvv;
            dot[2] += qr[512 + d] * kvv;
            dot[3] += qr[768 + d] * kvv;
        }

        #pragma unroll
        for (int qi = 0; qi < 4; qi++) {
            bool valid = (kp <= qp[qi]) && ((qp[qi] - kp) < window) && (ks == qsg[qi]);
            float lg = 50.f * tanhf(dot[qi] * 0.02f);
            lg = valid ? lg : -1e30f;
            float tm = lg;
            #pragma unroll
            for (int o = 16; o; o >>= 1) tm = fmaxf(tm, __shfl_xor_sync(0xffffffffu, tm, o));
            float nm = fmaxf(mval[qi], tm);
            float p = __expf(lg - nm);
            float psum = p;
            #pragma unroll
            for (int o = 16; o; o >>= 1) psum += __shfl_xor_sync(0xffffffffu, psum, o);
            float alpha = __expf(mval[qi] - nm);
            mval[qi] = nm;
            lval[qi] = lval[qi] * alpha + psum;
            #pragma unroll
            for (int t = 0; t < 8; t++) acc[qi][t] *= alpha;
            Ps[(w * 4 + qi) * 32 + lane] = p;
        }
        __syncwarp();

        for (int kk = 0; kk < 32; kk++) {
            float vr[8];
            #pragma unroll
            for (int t = 0; t < 8; t++) vr[t] = Vs[kk * KPAD + lane + 32 * t];
            #pragma unroll
            for (int qi = 0; qi < 4; qi++) {
                float pk = Ps[(w * 4 + qi) * 32 + kk];
                #pragma unroll
                for (int t = 0; t < 8; t++) acc[qi][t] += pk * vr[t];
            }
        }
    }

    #pragma unroll
    for (int qi = 0; qi < 4; qi++) {
        int qg = q0g + w * 4 + qi;
        float inv = 1.f / lval[qi];
        float* op = out + ((size_t)(b * SS + qg) * NHQ + h) * HD;
        #pragma unroll
        for (int t = 0; t < 8; t++) op[lane + 32 * t] = acc[qi][t] * inv;
    }
}

// ---------------- host-side orchestration ----------------
static void run_layer(const float* pre_attn, const float* post_attn,
                      const float* pre_ffw, const float* post_ffw,
                      const float* wq, const float* wk, const float* wv, const float* wo,
                      const float* wi0, const float* wi1, const float* wom,
                      const int* pos, const int* seg, int window,
                      float* x, float* h, float* qb, float* kb, float* vb,
                      float* att, float* tmp, float* ff) {
    rms_kernel<<<MM, 256>>>(x, pre_attn, h);
    sgemm_kernel<<<dim3((NHQ*HD)/128, MM/128), 256>>>(h, wq, qb, MM, NHQ*HD, DD, 0.0625f);
    sgemm_kernel<<<dim3((NHKV*HD)/128, MM/128), 256>>>(h, wk, kb, MM, NHKV*HD, DD, 1.f);
    sgemm_kernel<<<dim3((NHKV*HD)/128, MM/128), 256>>>(h, wv, vb, MM, NHKV*HD, DD, 1.f);
    {
        int tq = MM * NHQ * 128;
        rope_kernel<<<(tq + 255)/256, 256>>>(qb, pos, NHQ, tq);
        int tk = MM * NHKV * 128;
        rope_kernel<<<(tk + 255)/256, 256>>>(kb, pos, NHKV, tk);
    }
    attn_kernel<<<dim3(SS/32, NHQ, BB), 256, ATTN_SMEM_BYTES>>>(qb, kb, vb, pos, seg, att, window);
    sgemm_kernel<<<dim3(DD/128, MM/128), 256>>>(att, wo, tmp, MM, DD, NHQ*HD, 1.f);
    rms_add_kernel<<<MM, 256>>>(tmp, post_attn, x);
    rms_kernel<<<MM, 256>>>(x, pre_ffw, h);
    ffw_dual_kernel<<<dim3(FF/64, MM/128), 256>>>(h, wi0, wi1, ff, MM, FF, DD);
    sgemm_kernel<<<dim3(DD/128, MM/128), 256>>>(ff, wom, tmp, MM, DD, FF, 1.f);
    rms_add_kernel<<<MM, 256>>>(tmp, post_ffw, x);
}

extern "C" void kernel_launch(void* const* d_in, const int* in_sizes, int n_in,
                              void* d_out, int out_size) {
    const float* x_in = (const float*)d_in[0];
    const int* pos    = (const int*)d_in[1];
    const int* seg    = (const int*)d_in[2];
    const float* pre_attn_l  = (const float*)d_in[3];
    const float* post_attn_l = (const float*)d_in[4];
    const float* pre_ffw_l   = (const float*)d_in[5];
    const float* post_ffw_l  = (const float*)d_in[6];
    const float* wq_l  = (const float*)d_in[7];
    const float* wk_l  = (const float*)d_in[8];
    const float* wv_l  = (const float*)d_in[9];
    const float* wo_l  = (const float*)d_in[10];
    const float* wi0_l = (const float*)d_in[11];
    const float* wi1_l = (const float*)d_in[12];
    const float* wom_l = (const float*)d_in[13];
    const float* pre_attn_g  = (const float*)d_in[14];
    const float* post_attn_g = (const float*)d_in[15];
    const float* pre_ffw_g   = (const float*)d_in[16];
    const float* post_ffw_g  = (const float*)d_in[17];
    const float* wq_g  = (const float*)d_in[18];
    const float* wk_g  = (const float*)d_in[19];
    const float* wv_g  = (const float*)d_in[20];
    const float* wo_g  = (const float*)d_in[21];
    const float* wi0_g = (const float*)d_in[22];
    const float* wi1_g = (const float*)d_in[23];
    const float* wom_g = (const float*)d_in[24];

    float *px, *ph, *pq, *pk, *pv, *patt, *ptmp, *pff;
    cudaGetSymbolAddress((void**)&px,   g_x);
    cudaGetSymbolAddress((void**)&ph,   g_h);
    cudaGetSymbolAddress((void**)&pq,   g_q);
    cudaGetSymbolAddress((void**)&pk,   g_k);
    cudaGetSymbolAddress((void**)&pv,   g_v);
    cudaGetSymbolAddress((void**)&patt, g_att);
    cudaGetSymbolAddress((void**)&ptmp, g_tmp);
    cudaGetSymbolAddress((void**)&pff,  g_ff);

    cudaFuncSetAttribute(attn_kernel, cudaFuncAttributeMaxDynamicSharedMemorySize, ATTN_SMEM_BYTES);

    int n = MM * DD;
    copy_kernel<<<(n + 255)/256, 256>>>(px, x_in, n);

    run_layer(pre_attn_l, post_attn_l, pre_ffw_l, post_ffw_l,
              wq_l, wk_l, wv_l, wo_l, wi0_l, wi1_l, wom_l,
              pos, seg, /*window=*/1024,
              px, ph, pq, pk, pv, patt, ptmp, pff);

    run_layer(pre_attn_g, post_attn_g, pre_ffw_g, post_ffw_g,
              wq_g, wk_g, wv_g, wo_g, wi0_g, wi1_g, wom_g,
              pos, seg, /*window=*/SS,   // no window: max pos diff is S-1 < S
              px, ph, pq, pk, pv, patt, ptmp, pff);

    copy_kernel<<<(n + 255)/256, 256>>>((float*)d_out, px, n);
}

// round 11
// speedup vs baseline: 2.2493x; 2.2493x over previous
#include <cuda_runtime.h>
#include <math.h>
#include <stdint.h>

#define BB 2
#define SS 2048
#define DD 2304
#define NHQ 8
#define NHKV 4
#define HD 256
#define FF 9216
#define MM (BB*SS)   // 4096 rows

// ---------------- persistent scratch (no allocations allowed) ----------------
__device__ float g_x  [MM*DD];
__device__ float g_h  [MM*DD];
__device__ float g_q  [MM*NHQ*HD];
__device__ float g_k  [MM*NHKV*HD];
__device__ float g_v  [MM*NHKV*HD];
__device__ float g_att[MM*NHQ*HD];
__device__ float g_tmp[MM*DD];
__device__ float g_ff [MM*FF];
__device__ float g_ff2[MM*FF];

// ---------------- small helpers ----------------
__global__ void copy_kernel(float* __restrict__ dst, const float* __restrict__ src, int n) {
    int i = blockIdx.x * blockDim.x + threadIdx.x;
    if (i < n) dst[i] = src[i];
}

__global__ void rms_kernel(const float* __restrict__ in, const float* __restrict__ scale,
                           float* __restrict__ out) {
    int row = blockIdx.x;
    const float* r = in + (size_t)row * DD;
    float ss = 0.f;
    for (int i = threadIdx.x; i < DD; i += 256) { float v = r[i]; ss += v * v; }
    #pragma unroll
    for (int o = 16; o; o >>= 1) ss += __shfl_xor_sync(0xffffffffu, ss, o);
    __shared__ float red[8];
    if ((threadIdx.x & 31) == 0) red[threadIdx.x >> 5] = ss;
    __syncthreads();
    float tot = red[0]+red[1]+red[2]+red[3]+red[4]+red[5]+red[6]+red[7];
    float rs = rsqrtf(tot / (float)DD + 1e-6f);
    float* o = out + (size_t)row * DD;
    for (int i = threadIdx.x; i < DD; i += 256) o[i] = r[i] * rs * scale[i];
}

__global__ void rms_add_kernel(const float* __restrict__ a, const float* __restrict__ scale,
                               float* __restrict__ x) {
    int row = blockIdx.x;
    const float* r = a + (size_t)row * DD;
    float ss = 0.f;
    for (int i = threadIdx.x; i < DD; i += 256) { float v = r[i]; ss += v * v; }
    #pragma unroll
    for (int o = 16; o; o >>= 1) ss += __shfl_xor_sync(0xffffffffu, ss, o);
    __shared__ float red[8];
    if ((threadIdx.x & 31) == 0) red[threadIdx.x >> 5] = ss;
    __syncthreads();
    float tot = red[0]+red[1]+red[2]+red[3]+red[4]+red[5]+red[6]+red[7];
    float rs = rsqrtf(tot / (float)DD + 1e-6f);
    float* xo = x + (size_t)row * DD;
    for (int i = threadIdx.x; i < DD; i += 256) xo[i] += r[i] * rs * scale[i];
}

__device__ __forceinline__ float gelu_tanh(float x) {
    float x3 = x * x * x;
    return 0.5f * x * (1.f + tanhf(0.7978845608028654f * (x + 0.044715f * x3)));
}

// ---------------- tf32 tensor-core GEMM ----------------
// C[M,N] = epilogue(A[M,K] @ B[K,N]); row-major everything.
// Block tile 128x128, BK=32, 256 threads = 8 warps (4 along M x 2 along N),
// warp tile 32x64 -> 2x8 m16n8k8 tf32 mma fragments, fp32 accumulate.
// MODE 0: C = alpha * acc.   MODE 1: C = gelu(aux) * acc  (GeGLU fuse).

__device__ __forceinline__ uint32_t f2tf(float x) {
    uint32_t r;
    asm("cvt.rna.tf32.f32 %0, %1;" : "=r"(r) : "f"(x));
    return r;
}

__device__ __forceinline__ void mma8(float* c, const uint32_t* a, const uint32_t* b) {
    asm volatile("mma.sync.aligned.m16n8k8.row.col.f32.tf32.tf32.f32 "
        "{%0,%1,%2,%3},{%4,%5,%6,%7},{%8,%9},{%0,%1,%2,%3};"
        : "+f"(c[0]), "+f"(c[1]), "+f"(c[2]), "+f"(c[3])
        : "r"(a[0]), "r"(a[1]), "r"(a[2]), "r"(a[3]), "r"(b[0]), "r"(b[1]));
}

template<int MODE>
__global__ void __launch_bounds__(256) tf32_gemm(const float* __restrict__ A,
                                                 const float* __restrict__ B,
                                                 float* __restrict__ C,
                                                 const float* __restrict__ aux,
                                                 int M, int N, int K, float alpha) {
    __shared__ uint32_t As[128 * 32];   // A tile, swizzled: col ^ (4*(row&7))
    __shared__ uint32_t Bs[32 * 128];   // B tile, swizzled: col ^ (8*(row&3))

    int tid = threadIdx.x;
    int lane = tid & 31;
    int warp = tid >> 5;
    int wm = warp & 3;          // warp row: m offset wm*32
    int wn = warp >> 2;         // warp col: n offset wn*64
    int g = lane >> 2;          // groupID 0..7
    int t = lane & 3;           // thread-in-group 0..3

    int m0 = blockIdx.y * 128;
    int n0 = blockIdx.x * 128;

    // global-load register staging
    float4 va[4], vb[4];
    int arow = tid >> 3;            // 0..31
    int acol = (tid & 7) * 4;       // 0..28
    int brow = tid >> 5;            // 0..7
    int bcol = (tid & 31) * 4;      // 0..124

    float acc[2][8][4];
    #pragma unroll
    for (int mi = 0; mi < 2; mi++)
        #pragma unroll
        for (int ni = 0; ni < 8; ni++)
            #pragma unroll
            for (int j = 0; j < 4; j++) acc[mi][ni][j] = 0.f;

    // prologue: load tile 0
    #pragma unroll
    for (int p = 0; p < 4; p++) {
        int r = arow + p * 32;
        va[p] = *(const float4*)(A + (size_t)(m0 + r) * K + acol);
    }
    #pragma unroll
    for (int p = 0; p < 4; p++) {
        int r = brow + p * 8;
        vb[p] = *(const float4*)(B + (size_t)r * N + n0 + bcol);
    }
    #pragma unroll
    for (int p = 0; p < 4; p++) {
        int r = arow + p * 32;
        int sc = acol ^ (4 * (r & 7));
        uint4 u; u.x = f2tf(va[p].x); u.y = f2tf(va[p].y); u.z = f2tf(va[p].z); u.w = f2tf(va[p].w);
        *(uint4*)&As[r * 32 + sc] = u;
    }
    #pragma unroll
    for (int p = 0; p < 4; p++) {
        int r = brow + p * 8;
        int sc = bcol ^ (8 * (r & 3));
        uint4 u; u.x = f2tf(vb[p].x); u.y = f2tf(vb[p].y); u.z = f2tf(vb[p].z); u.w = f2tf(vb[p].w);
        *(uint4*)&Bs[r * 128 + sc] = u;
    }
    __syncthreads();

    for (int k0 = 0; k0 < K; k0 += 32) {
        bool more = (k0 + 32) < K;
        if (more) {
            #pragma unroll
            for (int p = 0; p < 4; p++) {
                int r = arow + p * 32;
                va[p] = *(const float4*)(A + (size_t)(m0 + r) * K + k0 + 32 + acol);
            }
            #pragma unroll
            for (int p = 0; p < 4; p++) {
                int r = brow + p * 8;
                vb[p] = *(const float4*)(B + (size_t)(k0 + 32 + r) * N + n0 + bcol);
            }
        }

        // compute 4 k-steps of 8 from smem
        #pragma unroll
        for (int kk = 0; kk < 32; kk += 8) {
            uint32_t af[2][4], bf[8][2];
            #pragma unroll
            for (int mi = 0; mi < 2; mi++) {
                int r0 = wm * 32 + mi * 16 + g;
                int c0 = (kk + t) ^ (4 * g);
                int c1 = (kk + t + 4) ^ (4 * g);
                af[mi][0] = As[r0 * 32 + c0];
                af[mi][1] = As[(r0 + 8) * 32 + c0];
                af[mi][2] = As[r0 * 32 + c1];
                af[mi][3] = As[(r0 + 8) * 32 + c1];
            }
            #pragma unroll
            for (int ni = 0; ni < 8; ni++) {
                int n = wn * 64 + ni * 8 + g;
                bf[ni][0] = Bs[(kk + t) * 128 + (n ^ (8 * t))];
                bf[ni][1] = Bs[(kk + t + 4) * 128 + (n ^ (8 * t))];
            }
            #pragma unroll
            for (int mi = 0; mi < 2; mi++)
                #pragma unroll
                for (int ni = 0; ni < 8; ni++)
                    mma8(acc[mi][ni], af[mi], bf[ni]);
        }

        if (more) {
            __syncthreads();
            #pragma unroll
            for (int p = 0; p < 4; p++) {
                int r = arow + p * 32;
                int sc = acol ^ (4 * (r & 7));
                uint4 u; u.x = f2tf(va[p].x); u.y = f2tf(va[p].y); u.z = f2tf(va[p].z); u.w = f2tf(va[p].w);
                *(uint4*)&As[r * 32 + sc] = u;
            }
            #pragma unroll
            for (int p = 0; p < 4; p++) {
                int r = brow + p * 8;
                int sc = bcol ^ (8 * (r & 3));
                uint4 u; u.x = f2tf(vb[p].x); u.y = f2tf(vb[p].y); u.z = f2tf(vb[p].z); u.w = f2tf(vb[p].w);
                *(uint4*)&Bs[r * 128 + sc] = u;
            }
            __syncthreads();
        }
    }

    // epilogue
    #pragma unroll
    for (int mi = 0; mi < 2; mi++) {
        #pragma unroll
        for (int ni = 0; ni < 8; ni++) {
            int row = m0 + wm * 32 + mi * 16 + g;
            int col = n0 + wn * 64 + ni * 8 + 2 * t;
            size_t i0 = (size_t)row * N + col;
            size_t i1 = (size_t)(row + 8) * N + col;
            if (MODE == 0) {
                float2 v0 = make_float2(acc[mi][ni][0] * alpha, acc[mi][ni][1] * alpha);
                float2 v1 = make_float2(acc[mi][ni][2] * alpha, acc[mi][ni][3] * alpha);
                *(float2*)(C + i0) = v0;
                *(float2*)(C + i1) = v1;
            } else {
                float2 a0 = *(const float2*)(aux + i0);
                float2 a1 = *(const float2*)(aux + i1);
                float2 v0 = make_float2(gelu_tanh(a0.x) * acc[mi][ni][0],
                                        gelu_tanh(a0.y) * acc[mi][ni][1]);
                float2 v1 = make_float2(gelu_tanh(a1.x) * acc[mi][ni][2],
                                        gelu_tanh(a1.y) * acc[mi][ni][3]);
                *(float2*)(C + i0) = v0;
                *(float2*)(C + i1) = v1;
            }
        }
    }
}

// ---------------- RoPE (in-place), half = 128 ----------------
__global__ void rope_kernel(float* __restrict__ x, const int* __restrict__ positions, int H, int total) {
    int idx = blockIdx.x * blockDim.x + threadIdx.x;
    if (idx >= total) return;
    int i = idx & 127;
    int h = (idx >> 7) % H;
    int s = (idx / (128 * H)) % SS;
    int b = idx / (128 * H * SS);
    int p = positions[b * SS + s];
    double f = exp2(-(double)i * (13.287712379549449 / 128.0));
    double ang = (double)p * f;
    double sd, cd;
    sincos(ang, &sd, &cd);
    float sn = (float)sd, cs = (float)cd;
    size_t base = ((size_t)(b * SS + s) * H + h) * HD;
    float x1 = x[base + i], x2 = x[base + 128 + i];
    x[base + i]       = x1 * cs - x2 * sn;
    x[base + 128 + i] = x2 * cs + x1 * sn;
}

// ---------------- attention: online softmax, softcap, causal+window+segment ----------------
#define KPAD 257
#define ATTN_SMEM_FLOATS (32*256 + 32*KPAD + 32*KPAD + 8*4*32 + 64)
#define ATTN_SMEM_BYTES (ATTN_SMEM_FLOATS * 4)

__global__ void __launch_bounds__(256) attn_kernel(const float* __restrict__ q,
                                                   const float* __restrict__ k,
                                                   const float* __restrict__ v,
                                                   const int* __restrict__ pos,
                                                   const int* __restrict__ seg,
                                                   float* __restrict__ out,
                                                   int window) {
    extern __shared__ float sm[];
    float* Qs = sm;
    float* Ks = Qs + 32 * 256;
    float* Vs = Ks + 32 * KPAD;
    float* Ps = Vs + 32 * KPAD;
    int* kposs = (int*)(Ps + 8 * 4 * 32);
    int* ksegs = kposs + 32;

    int b = blockIdx.z, h = blockIdx.y, qt = blockIdx.x;
    int kvh = h / (NHQ / NHKV);
    int tid = threadIdx.x, w = tid >> 5, lane = tid & 31;
    int q0g = qt * 32;

    for (int t = tid; t < 32 * 256; t += 256) {
        int lq = t >> 8, d = t & 255;
        Qs[t] = q[((size_t)(b * SS + q0g + lq) * NHQ + h) * HD + d];
    }

    int qp[4], qsg[4];
    #pragma unroll
    for (int qi = 0; qi < 4; qi++) {
        int qg = q0g + w * 4 + qi;
        qp[qi]  = pos[b * SS + qg];
        qsg[qi] = seg[b * SS + qg];
    }

    float mval[4], lval[4], acc[4][8];
    #pragma unroll
    for (int qi = 0; qi < 4; qi++) {
        mval[qi] = -1e30f; lval[qi] = 0.f;
        #pragma unroll
        for (int t = 0; t < 8; t++) acc[qi][t] = 0.f;
    }

    int kend = q0g + 32;
    int kstart = 0;
    { int lo = q0g - (window - 1); if (lo > 0) kstart = lo & ~31; }

    for (int kb = kstart; kb < kend; kb += 32) {
        __syncthreads();
        for (int t = tid; t < 32 * 256; t += 256) {
            int kk = t >> 8, d = t & 255;
            size_t gi = ((size_t)(b * SS + kb + kk) * NHKV + kvh) * HD + d;
            Ks[kk * KPAD + d] = k[gi];
            Vs[kk * KPAD + d] = v[gi];
        }
        if (tid < 32) { kposs[tid] = pos[b * SS + kb + tid]; ksegs[tid] = seg[b * SS + kb + tid]; }
        __syncthreads();

        int kp = kposs[lane], ks = ksegs[lane];
        const float* kr = Ks + lane * KPAD;
        const float* qr = Qs + (w * 4) * 256;
        float dot[4] = {0.f, 0.f, 0.f, 0.f};
        #pragma unroll 8
        for (int d = 0; d < 256; d++) {
            float kvv = kr[d];
            dot[0] += qr[d]       * kvv;
            dot[1] += qr[256 + d] * kvv;
            dot[2] += qr[512 + d] * kvv;
            dot[3] += qr[768 + d] * kvv;
        }

        #pragma unroll
        for (int qi = 0; qi < 4; qi++) {
            bool valid = (kp <= qp[qi]) && ((qp[qi] - kp) < window) && (ks == qsg[qi]);
            float lg = 50.f * tanhf(dot[qi] * 0.02f);
            lg = valid ? lg : -1e30f;
            float tm = lg;
            #pragma unroll
            for (int o = 16; o; o >>= 1) tm = fmaxf(tm, __shfl_xor_sync(0xffffffffu, tm, o));
            float nm = fmaxf(mval[qi], tm);
            float p = __expf(lg - nm);
            float psum = p;
            #pragma unroll
            for (int o = 16; o; o >>= 1) psum += __shfl_xor_sync(0xffffffffu, psum, o);
            float alpha = __expf(mval[qi] - nm);
            mval[qi] = nm;
            lval[qi] = lval[qi] * alpha + psum;
            #pragma unroll
            for (int t = 0; t < 8; t++) acc[qi][t] *= alpha;
            Ps[(w * 4 + qi) * 32 + lane] = p;
        }
        __syncwarp();

        for (int kk = 0; kk < 32; kk++) {
            float vr[8];
            #pragma unroll
            for (int t = 0; t < 8; t++) vr[t] = Vs[kk * KPAD + lane + 32 * t];
            #pragma unroll
            for (int qi = 0; qi < 4; qi++) {
                float pk = Ps[(w * 4 + qi) * 32 + kk];
                #pragma unroll
                for (int t = 0; t < 8; t++) acc[qi][t] += pk * vr[t];
            }
        }
    }

    #pragma unroll
    for (int qi = 0; qi < 4; qi++) {
        int qg = q0g + w * 4 + qi;
        float inv = 1.f / lval[qi];
        float* op = out + ((size_t)(b * SS + qg) * NHQ + h) * HD;
        #pragma unroll
        for (int t = 0; t < 8; t++) op[lane + 32 * t] = acc[qi][t] * inv;
    }
}

// ---------------- host-side orchestration ----------------
static void run_layer(const float* pre_attn, const float* post_attn,
                      const float* pre_ffw, const float* post_ffw,
                      const float* wq, const float* wk, const float* wv, const float* wo,
                      const float* wi0, const float* wi1, const float* wom,
                      const int* pos, const int* seg, int window,
                      float* x, float* h, float* qb, float* kb, float* vb,
                      float* att, float* tmp, float* ff, float* ff2) {
    rms_kernel<<<MM, 256>>>(x, pre_attn, h);
    tf32_gemm<0><<<dim3((NHQ*HD)/128, MM/128), 256>>>(h, wq, qb, nullptr, MM, NHQ*HD, DD, 0.0625f);
    tf32_gemm<0><<<dim3((NHKV*HD)/128, MM/128), 256>>>(h, wk, kb, nullptr, MM, NHKV*HD, DD, 1.f);
    tf32_gemm<0><<<dim3((NHKV*HD)/128, MM/128), 256>>>(h, wv, vb, nullptr, MM, NHKV*HD, DD, 1.f);
    {
        int tq = MM * NHQ * 128;
        rope_kernel<<<(tq + 255)/256, 256>>>(qb, pos, NHQ, tq);
        int tk = MM * NHKV * 128;
        rope_kernel<<<(tk + 255)/256, 256>>>(kb, pos, NHKV, tk);
    }
    attn_kernel<<<dim3(SS/32, NHQ, BB), 256, ATTN_SMEM_BYTES>>>(qb, kb, vb, pos, seg, att, window);
    tf32_gemm<0><<<dim3(DD/128, MM/128), 256>>>(att, wo, tmp, nullptr, MM, DD, NHQ*HD, 1.f);
    rms_add_kernel<<<MM, 256>>>(tmp, post_attn, x);
    rms_kernel<<<MM, 256>>>(x, pre_ffw, h);
    tf32_gemm<0><<<dim3(FF/128, MM/128), 256>>>(h, wi0, ff, nullptr, MM, FF, DD, 1.f);
    tf32_gemm<1><<<dim3(FF/128, MM/128), 256>>>(h, wi1, ff2, ff, MM, FF, DD, 1.f);
    tf32_gemm<0><<<dim3(DD/128, MM/128), 256>>>(ff2, wom, tmp, nullptr, MM, DD, FF, 1.f);
    rms_add_kernel<<<MM, 256>>>(tmp, post_ffw, x);
}

extern "C" void kernel_launch(void* const* d_in, const int* in_sizes, int n_in,
                              void* d_out, int out_size) {
    const float* x_in = (const float*)d_in[0];
    const int* pos    = (const int*)d_in[1];
    const int* seg    = (const int*)d_in[2];
    const float* pre_attn_l  = (const float*)d_in[3];
    const float* post_attn_l = (const float*)d_in[4];
    const float* pre_ffw_l   = (const float*)d_in[5];
    const float* post_ffw_l  = (const float*)d_in[6];
    const float* wq_l  = (const float*)d_in[7];
    const float* wk_l  = (const float*)d_in[8];
    const float* wv_l  = (const float*)d_in[9];
    const float* wo_l  = (const float*)d_in[10];
    const float* wi0_l = (const float*)d_in[11];
    const float* wi1_l = (const float*)d_in[12];
    const float* wom_l = (const float*)d_in[13];
    const float* pre_attn_g  = (const float*)d_in[14];
    const float* post_attn_g = (const float*)d_in[15];
    const float* pre_ffw_g   = (const float*)d_in[16];
    const float* post_ffw_g  = (const float*)d_in[17];
    const float* wq_g  = (const float*)d_in[18];
    const float* wk_g  = (const float*)d_in[19];
    const float* wv_g  = (const float*)d_in[20];
    const float* wo_g  = (const float*)d_in[21];
    const float* wi0_g = (const float*)d_in[22];
    const float* wi1_g = (const float*)d_in[23];
    const float* wom_g = (const float*)d_in[24];

    float *px, *ph, *pq, *pk, *pv, *patt, *ptmp, *pff, *pff2;
    cudaGetSymbolAddress((void**)&px,   g_x);
    cudaGetSymbolAddress((void**)&ph,   g_h);
    cudaGetSymbolAddress((void**)&pq,   g_q);
    cudaGetSymbolAddress((void**)&pk,   g_k);
    cudaGetSymbolAddress((void**)&pv,   g_v);
    cudaGetSymbolAddress((void**)&patt, g_att);
    cudaGetSymbolAddress((void**)&ptmp, g_tmp);
    cudaGetSymbolAddress((void**)&pff,  g_ff);
    cudaGetSymbolAddress((void**)&pff2, g_ff2);

    cudaFuncSetAttribute(attn_kernel, cudaFuncAttributeMaxDynamicSharedMemorySize, ATTN_SMEM_BYTES);

    int n = MM * DD;
    copy_kernel<<<(n + 255)/256, 256>>>(px, x_in, n);

    run_layer(pre_attn_l, post_attn_l, pre_ffw_l, post_ffw_l,
              wq_l, wk_l, wv_l, wo_l, wi0_l, wi1_l, wom_l,
              pos, seg, /*window=*/1024,
              px, ph, pq, pk, pv, patt, ptmp, pff, pff2);

    run_layer(pre_attn_g, post_attn_g, pre_ffw_g, post_ffw_g,
              wq_g, wk_g, wv_g, wo_g, wi0_g, wi1_g, wom_g,
              pos, seg, /*window=*/SS,
              px, ph, pq, pk, pv, patt, ptmp, pff, pff2);

    copy_kernel<<<(n + 255)/256, 256>>>((float*)d_out, px, n);
}

// round 12
// speedup vs baseline: 2.6387x; 1.1731x over previous
#include <cuda_runtime.h>
#include <math.h>
#include <stdint.h>

#define BB 2
#define SS 2048
#define DD 2304
#define NHQ 8
#define NHKV 4
#define HD 256
#define FF 9216
#define MM (BB*SS)   // 4096 rows

// ---------------- persistent scratch (no allocations allowed) ----------------
__device__ float g_x  [MM*DD];
__device__ float g_h  [MM*DD];
__device__ float g_q  [MM*NHQ*HD];
__device__ float g_k  [MM*NHKV*HD];
__device__ float g_v  [MM*NHKV*HD];
__device__ float g_att[MM*NHQ*HD];
__device__ float g_tmp[MM*DD];
__device__ float g_ff [MM*FF];
__device__ float g_ff2[MM*FF];
// pre-rounded (tf32) weights, reused across both layers (re-rounded per layer)
__device__ uint32_t g_wq [DD*NHQ*HD];
__device__ uint32_t g_wk [DD*NHKV*HD];
__device__ uint32_t g_wv [DD*NHKV*HD];
__device__ uint32_t g_wo [NHQ*HD*DD];
__device__ uint32_t g_wi0[DD*FF];
__device__ uint32_t g_wi1[DD*FF];
__device__ uint32_t g_wom[FF*DD];

__device__ __forceinline__ uint32_t f2tf(float x) {
    uint32_t r;
    asm("cvt.rna.tf32.f32 %0, %1;" : "=r"(r) : "f"(x));
    return r;
}

// ---------------- small helpers ----------------
__global__ void copy_kernel(float* __restrict__ dst, const float* __restrict__ src, int n) {
    int i = blockIdx.x * blockDim.x + threadIdx.x;
    if (i < n) dst[i] = src[i];
}

// vectorized tf32 rounding pass (weights)
__global__ void round_tf32_kernel(const float4* __restrict__ in, uint4* __restrict__ out, int n4) {
    int i = blockIdx.x * blockDim.x + threadIdx.x;
    if (i < n4) {
        float4 v = in[i];
        uint4 u;
        u.x = f2tf(v.x); u.y = f2tf(v.y); u.z = f2tf(v.z); u.w = f2tf(v.w);
        out[i] = u;
    }
}

// out[row] = tf32_round(in[row] * rsqrt(mean(in^2)+eps) * scale)   (GEMM A operand)
__global__ void rms_kernel(const float* __restrict__ in, const float* __restrict__ scale,
                           float* __restrict__ out) {
    int row = blockIdx.x;
    const float* r = in + (size_t)row * DD;
    float ss = 0.f;
    for (int i = threadIdx.x; i < DD; i += 256) { float v = r[i]; ss += v * v; }
    #pragma unroll
    for (int o = 16; o; o >>= 1) ss += __shfl_xor_sync(0xffffffffu, ss, o);
    __shared__ float red[8];
    if ((threadIdx.x & 31) == 0) red[threadIdx.x >> 5] = ss;
    __syncthreads();
    float tot = red[0]+red[1]+red[2]+red[3]+red[4]+red[5]+red[6]+red[7];
    float rs = rsqrtf(tot / (float)DD + 1e-6f);
    float* o = out + (size_t)row * DD;
    for (int i = threadIdx.x; i < DD; i += 256)
        o[i] = __uint_as_float(f2tf(r[i] * rs * scale[i]));
}

__global__ void rms_add_kernel(const float* __restrict__ a, const float* __restrict__ scale,
                               float* __restrict__ x) {
    int row = blockIdx.x;
    const float* r = a + (size_t)row * DD;
    float ss = 0.f;
    for (int i = threadIdx.x; i < DD; i += 256) { float v = r[i]; ss += v * v; }
    #pragma unroll
    for (int o = 16; o; o >>= 1) ss += __shfl_xor_sync(0xffffffffu, ss, o);
    __shared__ float red[8];
    if ((threadIdx.x & 31) == 0) red[threadIdx.x >> 5] = ss;
    __syncthreads();
    float tot = red[0]+red[1]+red[2]+red[3]+red[4]+red[5]+red[6]+red[7];
    float rs = rsqrtf(tot / (float)DD + 1e-6f);
    float* xo = x + (size_t)row * DD;
    for (int i = threadIdx.x; i < DD; i += 256) xo[i] += r[i] * rs * scale[i];
}

__device__ __forceinline__ float gelu_tanh(float x) {
    float x3 = x * x * x;
    return 0.5f * x * (1.f + tanhf(0.7978845608028654f * (x + 0.044715f * x3)));
}

// ---------------- tf32 tensor-core GEMM, cp.async 3-stage pipeline ----------------
// Inputs A,B are PRE-ROUNDED tf32 bit patterns. No cvt in the kernel.
// Block tile 128x128, BK=32, 256 threads = 8 warps (4 M x 2 N), warp tile 32x64.
// MODE 0: C = alpha*acc (fp32).  MODE 1: C = tf32_round(gelu(aux) * acc).

#define GSTAGES 3
#define SMEM_GEMM (GSTAGES * (128*32 + 32*128) * 4)

__device__ __forceinline__ void mma8(float* c, const uint32_t* a, const uint32_t* b) {
    asm volatile("mma.sync.aligned.m16n8k8.row.col.f32.tf32.tf32.f32 "
        "{%0,%1,%2,%3},{%4,%5,%6,%7},{%8,%9},{%0,%1,%2,%3};"
        : "+f"(c[0]), "+f"(c[1]), "+f"(c[2]), "+f"(c[3])
        : "r"(a[0]), "r"(a[1]), "r"(a[2]), "r"(a[3]), "r"(b[0]), "r"(b[1]));
}

template<int MODE>
__global__ void __launch_bounds__(256) tf32_gemm(const uint32_t* __restrict__ A,
                                                 const uint32_t* __restrict__ B,
                                                 float* __restrict__ C,
                                                 const float* __restrict__ aux,
                                                 int M, int N, int K, float alpha) {
    extern __shared__ uint32_t smem_[];
    uint32_t* As = smem_;                          // [GSTAGES][128*32], col ^ 4*(row&7)
    uint32_t* Bs = smem_ + GSTAGES * 128 * 32;     // [GSTAGES][32*128], col ^ 8*(row&3)

    int tid = threadIdx.x;
    int lane = tid & 31;
    int warp = tid >> 5;
    int wm = warp & 3;
    int wn = warp >> 2;
    int g = lane >> 2;
    int t = lane & 3;

    int m0 = blockIdx.y * 128;
    int n0 = blockIdx.x * 128;

    int arow = tid >> 3;            // 0..31
    int acol = (tid & 7) * 4;       // 0..28
    int brow = tid >> 5;            // 0..7
    int bcol = (tid & 31) * 4;      // 0..124

    float acc[2][8][4];
    #pragma unroll
    for (int mi = 0; mi < 2; mi++)
        #pragma unroll
        for (int ni = 0; ni < 8; ni++)
            #pragma unroll
            for (int j = 0; j < 4; j++) acc[mi][ni][j] = 0.f;

    auto load_stage = [&](int k0, int s) {
        uint32_t* Ad = As + s * (128 * 32);
        uint32_t* Bd = Bs + s * (32 * 128);
        #pragma unroll
        for (int p = 0; p < 4; p++) {
            int r = arow + p * 32;
            int sc = acol ^ (4 * (r & 7));
            uint32_t d = (uint32_t)__cvta_generic_to_shared(Ad + r * 32 + sc);
            asm volatile("cp.async.cg.shared.global [%0], [%1], 16;\n"
                         :: "r"(d), "l"(A + (size_t)(m0 + r) * K + k0 + acol));
        }
        #pragma unroll
        for (int p = 0; p < 4; p++) {
            int r = brow + p * 8;
            int sc = bcol ^ (8 * (r & 3));
            uint32_t d = (uint32_t)__cvta_generic_to_shared(Bd + r * 128 + sc);
            asm volatile("cp.async.cg.shared.global [%0], [%1], 16;\n"
                         :: "r"(d), "l"(B + (size_t)(k0 + r) * N + n0 + bcol));
        }
    };

    int nk = K / 32;
    load_stage(0, 0);
    asm volatile("cp.async.commit_group;\n" ::);
    load_stage(32, 1);
    asm volatile("cp.async.commit_group;\n" ::);

    for (int ki = 0; ki < nk; ki++) {
        asm volatile("cp.async.wait_group 1;\n" ::);
        __syncthreads();
        // prefetch stage ki+2 (slot computed at iter ki-1; barrier above ordered it)
        if (ki + 2 < nk) load_stage((ki + 2) * 32, (ki + 2) % GSTAGES);
        asm volatile("cp.async.commit_group;\n" ::);

        const uint32_t* Ac = As + (ki % GSTAGES) * (128 * 32);
        const uint32_t* Bc = Bs + (ki % GSTAGES) * (32 * 128);

        #pragma unroll
        for (int kk = 0; kk < 32; kk += 8) {
            uint32_t af[2][4], bf[8][2];
            #pragma unroll
            for (int mi = 0; mi < 2; mi++) {
                int r0 = wm * 32 + mi * 16 + g;
                int c0 = (kk + t) ^ (4 * g);
                int c1 = (kk + t + 4) ^ (4 * g);
                af[mi][0] = Ac[r0 * 32 + c0];
                af[mi][1] = Ac[(r0 + 8) * 32 + c0];
                af[mi][2] = Ac[r0 * 32 + c1];
                af[mi][3] = Ac[(r0 + 8) * 32 + c1];
            }
            #pragma unroll
            for (int ni = 0; ni < 8; ni++) {
                int n = wn * 64 + ni * 8 + g;
                bf[ni][0] = Bc[(kk + t) * 128 + (n ^ (8 * t))];
                bf[ni][1] = Bc[(kk + t + 4) * 128 + (n ^ (8 * t))];
            }
            #pragma unroll
            for (int mi = 0; mi < 2; mi++)
                #pragma unroll
                for (int ni = 0; ni < 8; ni++)
                    mma8(acc[mi][ni], af[mi], bf[ni]);
        }
    }

    // epilogue
    #pragma unroll
    for (int mi = 0; mi < 2; mi++) {
        #pragma unroll
        for (int ni = 0; ni < 8; ni++) {
            int row = m0 + wm * 32 + mi * 16 + g;
            int col = n0 + wn * 64 + ni * 8 + 2 * t;
            size_t i0 = (size_t)row * N + col;
            size_t i1 = (size_t)(row + 8) * N + col;
            if (MODE == 0) {
                float2 v0 = make_float2(acc[mi][ni][0] * alpha, acc[mi][ni][1] * alpha);
                float2 v1 = make_float2(acc[mi][ni][2] * alpha, acc[mi][ni][3] * alpha);
                *(float2*)(C + i0) = v0;
                *(float2*)(C + i1) = v1;
            } else {
                float2 a0 = *(const float2*)(aux + i0);
                float2 a1 = *(const float2*)(aux + i1);
                float2 v0 = make_float2(__uint_as_float(f2tf(gelu_tanh(a0.x) * acc[mi][ni][0])),
                                        __uint_as_float(f2tf(gelu_tanh(a0.y) * acc[mi][ni][1])));
                float2 v1 = make_float2(__uint_as_float(f2tf(gelu_tanh(a1.x) * acc[mi][ni][2])),
                                        __uint_as_float(f2tf(gelu_tanh(a1.y) * acc[mi][ni][3])));
                *(float2*)(C + i0) = v0;
                *(float2*)(C + i1) = v1;
            }
        }
    }
}

// ---------------- RoPE (in-place), half = 128 ----------------
__global__ void rope_kernel(float* __restrict__ x, const int* __restrict__ positions, int H, int total) {
    int idx = blockIdx.x * blockDim.x + threadIdx.x;
    if (idx >= total) return;
    int i = idx & 127;
    int h = (idx >> 7) % H;
    int s = (idx / (128 * H)) % SS;
    int b = idx / (128 * H * SS);
    int p = positions[b * SS + s];
    double f = exp2(-(double)i * (13.287712379549449 / 128.0));
    double ang = (double)p * f;
    double sd, cd;
    sincos(ang, &sd, &cd);
    float sn = (float)sd, cs = (float)cd;
    size_t base = ((size_t)(b * SS + s) * H + h) * HD;
    float x1 = x[base + i], x2 = x[base + 128 + i];
    x[base + i]       = x1 * cs - x2 * sn;
    x[base + 128 + i] = x2 * cs + x1 * sn;
}

// ---------------- attention: online softmax, softcap, causal+window+segment ----------------
#define KPAD 257
#define ATTN_SMEM_FLOATS (32*256 + 32*KPAD + 32*KPAD + 8*4*32 + 64)
#define ATTN_SMEM_BYTES (ATTN_SMEM_FLOATS * 4)

__global__ void __launch_bounds__(256) attn_kernel(const float* __restrict__ q,
                                                   const float* __restrict__ k,
                                                   const float* __restrict__ v,
                                                   const int* __restrict__ pos,
                                                   const int* __restrict__ seg,
                                                   float* __restrict__ out,
                                                   int window) {
    extern __shared__ float sm[];
    float* Qs = sm;
    float* Ks = Qs + 32 * 256;
    float* Vs = Ks + 32 * KPAD;
    float* Ps = Vs + 32 * KPAD;
    int* kposs = (int*)(Ps + 8 * 4 * 32);
    int* ksegs = kposs + 32;

    int b = blockIdx.z, h = blockIdx.y, qt = blockIdx.x;
    int kvh = h / (NHQ / NHKV);
    int tid = threadIdx.x, w = tid >> 5, lane = tid & 31;
    int q0g = qt * 32;

    for (int t = tid; t < 32 * 256; t += 256) {
        int lq = t >> 8, d = t & 255;
        Qs[t] = q[((size_t)(b * SS + q0g + lq) * NHQ + h) * HD + d];
    }

    int qp[4], qsg[4];
    #pragma unroll
    for (int qi = 0; qi < 4; qi++) {
        int qg = q0g + w * 4 + qi;
        qp[qi]  = pos[b * SS + qg];
        qsg[qi] = seg[b * SS + qg];
    }

    float mval[4], lval[4], acc[4][8];
    #pragma unroll
    for (int qi = 0; qi < 4; qi++) {
        mval[qi] = -1e30f; lval[qi] = 0.f;
        #pragma unroll
        for (int t = 0; t < 8; t++) acc[qi][t] = 0.f;
    }

    int kend = q0g + 32;
    int kstart = 0;
    { int lo = q0g - (window - 1); if (lo > 0) kstart = lo & ~31; }

    for (int kb = kstart; kb < kend; kb += 32) {
        __syncthreads();
        for (int t = tid; t < 32 * 256; t += 256) {
            int kk = t >> 8, d = t & 255;
            size_t gi = ((size_t)(b * SS + kb + kk) * NHKV + kvh) * HD + d;
            Ks[kk * KPAD + d] = k[gi];
            Vs[kk * KPAD + d] = v[gi];
        }
        if (tid < 32) { kposs[tid] = pos[b * SS + kb + tid]; ksegs[tid] = seg[b * SS + kb + tid]; }
        __syncthreads();

        int kp = kposs[lane], ks = ksegs[lane];
        const float* kr = Ks + lane * KPAD;
        const float* qr = Qs + (w * 4) * 256;
        float dot[4] = {0.f, 0.f, 0.f, 0.f};
        #pragma unroll 8
        for (int d = 0; d < 256; d++) {
            float kvv = kr[d];
            dot[0] += qr[d]       * kvv;
            dot[1] += qr[256 + d] * kvv;
            dot[2] += qr[512 + d] * kvv;
            dot[3] += qr[768 + d] * kvv;
        }

        #pragma unroll
        for (int qi = 0; qi < 4; qi++) {
            bool valid = (kp <= qp[qi]) && ((qp[qi] - kp) < window) && (ks == qsg[qi]);
            float lg = 50.f * tanhf(dot[qi] * 0.02f);
            lg = valid ? lg : -1e30f;
            float tm = lg;
            #pragma unroll
            for (int o = 16; o; o >>= 1) tm = fmaxf(tm, __shfl_xor_sync(0xffffffffu, tm, o));
            float nm = fmaxf(mval[qi], tm);
            float p = __expf(lg - nm);
            float psum = p;
            #pragma unroll
            for (int o = 16; o; o >>= 1) psum += __shfl_xor_sync(0xffffffffu, psum, o);
            float alpha = __expf(mval[qi] - nm);
            mval[qi] = nm;
            lval[qi] = lval[qi] * alpha + psum;
            #pragma unroll
            for (int t = 0; t < 8; t++) acc[qi][t] *= alpha;
            Ps[(w * 4 + qi) * 32 + lane] = p;
        }
        __syncwarp();

        for (int kk = 0; kk < 32; kk++) {
            float vr[8];
            #pragma unroll
            for (int t = 0; t < 8; t++) vr[t] = Vs[kk * KPAD + lane + 32 * t];
            #pragma unroll
            for (int qi = 0; qi < 4; qi++) {
                float pk = Ps[(w * 4 + qi) * 32 + kk];
                #pragma unroll
                for (int t = 0; t < 8; t++) acc[qi][t] += pk * vr[t];
            }
        }
    }

    // tf32-round outputs: this buffer is the A operand of the O-projection GEMM
    #pragma unroll
    for (int qi = 0; qi < 4; qi++) {
        int qg = q0g + w * 4 + qi;
        float inv = 1.f / lval[qi];
        float* op = out + ((size_t)(b * SS + qg) * NHQ + h) * HD;
        #pragma unroll
        for (int t = 0; t < 8; t++)
            op[lane + 32 * t] = __uint_as_float(f2tf(acc[qi][t] * inv));
    }
}

// ---------------- host-side orchestration ----------------
static void round_weights(const float* wq, const float* wk, const float* wv, const float* wo,
                          const float* wi0, const float* wi1, const float* wom,
                          uint32_t* pwq, uint32_t* pwk, uint32_t* pwv, uint32_t* pwo,
                          uint32_t* pwi0, uint32_t* pwi1, uint32_t* pwom) {
    auto rnd = [](const float* in, uint32_t* out, int n) {
        int n4 = n / 4;
        round_tf32_kernel<<<(n4 + 255) / 256, 256>>>((const float4*)in, (uint4*)out, n4);
    };
    rnd(wq,  pwq,  DD * NHQ * HD);
    rnd(wk,  pwk,  DD * NHKV * HD);
    rnd(wv,  pwv,  DD * NHKV * HD);
    rnd(wo,  pwo,  NHQ * HD * DD);
    rnd(wi0, pwi0, DD * FF);
    rnd(wi1, pwi1, DD * FF);
    rnd(wom, pwom, FF * DD);
}

static void run_layer(const float* pre_attn, const float* post_attn,
                      const float* pre_ffw, const float* post_ffw,
                      const float* wq, const float* wk, const float* wv, const float* wo,
                      const float* wi0, const float* wi1, const float* wom,
                      const int* pos, const int* seg, int window,
                      float* x, float* h, float* qb, float* kb, float* vb,
                      float* att, float* tmp, float* ff, float* ff2,
                      uint32_t* pwq, uint32_t* pwk, uint32_t* pwv, uint32_t* pwo,
                      uint32_t* pwi0, uint32_t* pwi1, uint32_t* pwom) {
    round_weights(wq, wk, wv, wo, wi0, wi1, wom, pwq, pwk, pwv, pwo, pwi0, pwi1, pwom);

    rms_kernel<<<MM, 256>>>(x, pre_attn, h);
    tf32_gemm<0><<<dim3((NHQ*HD)/128, MM/128), 256, SMEM_GEMM>>>(
        (const uint32_t*)h, pwq, qb, nullptr, MM, NHQ*HD, DD, 0.0625f);
    tf32_gemm<0><<<dim3((NHKV*HD)/128, MM/128), 256, SMEM_GEMM>>>(
        (const uint32_t*)h, pwk, kb, nullptr, MM, NHKV*HD, DD, 1.f);
    tf32_gemm<0><<<dim3((NHKV*HD)/128, MM/128), 256, SMEM_GEMM>>>(
        (const uint32_t*)h, pwv, vb, nullptr, MM, NHKV*HD, DD, 1.f);
    {
        int tq = MM * NHQ * 128;
        rope_kernel<<<(tq + 255)/256, 256>>>(qb, pos, NHQ, tq);
        int tk = MM * NHKV * 128;
        rope_kernel<<<(tk + 255)/256, 256>>>(kb, pos, NHKV, tk);
    }
    attn_kernel<<<dim3(SS/32, NHQ, BB), 256, ATTN_SMEM_BYTES>>>(qb, kb, vb, pos, seg, att, window);
    tf32_gemm<0><<<dim3(DD/128, MM/128), 256, SMEM_GEMM>>>(
        (const uint32_t*)att, pwo, tmp, nullptr, MM, DD, NHQ*HD, 1.f);
    rms_add_kernel<<<MM, 256>>>(tmp, post_attn, x);
    rms_kernel<<<MM, 256>>>(x, pre_ffw, h);
    tf32_gemm<0><<<dim3(FF/128, MM/128), 256, SMEM_GEMM>>>(
        (const uint32_t*)h, pwi0, ff, nullptr, MM, FF, DD, 1.f);
    tf32_gemm<1><<<dim3(FF/128, MM/128), 256, SMEM_GEMM>>>(
        (const uint32_t*)h, pwi1, ff2, ff, MM, FF, DD, 1.f);
    tf32_gemm<0><<<dim3(DD/128, MM/128), 256, SMEM_GEMM>>>(
        (const uint32_t*)ff2, pwom, tmp, nullptr, MM, DD, FF, 1.f);
    rms_add_kernel<<<MM, 256>>>(tmp, post_ffw, x);
}

extern "C" void kernel_launch(void* const* d_in, const int* in_sizes, int n_in,
                              void* d_out, int out_size) {
    const float* x_in = (const float*)d_in[0];
    const int* pos    = (const int*)d_in[1];
    const int* seg    = (const int*)d_in[2];
    const float* pre_attn_l  = (const float*)d_in[3];
    const float* post_attn_l = (const float*)d_in[4];
    const float* pre_ffw_l   = (const float*)d_in[5];
    const float* post_ffw_l  = (const float*)d_in[6];
    const float* wq_l  = (const float*)d_in[7];
    const float* wk_l  = (const float*)d_in[8];
    const float* wv_l  = (const float*)d_in[9];
    const float* wo_l  = (const float*)d_in[10];
    const float* wi0_l = (const float*)d_in[11];
    const float* wi1_l = (const float*)d_in[12];
    const float* wom_l = (const float*)d_in[13];
    const float* pre_attn_g  = (const float*)d_in[14];
    const float* post_attn_g = (const float*)d_in[15];
    const float* pre_ffw_g   = (const float*)d_in[16];
    const float* post_ffw_g  = (const float*)d_in[17];
    const float* wq_g  = (const float*)d_in[18];
    const float* wk_g  = (const float*)d_in[19];
    const float* wv_g  = (const float*)d_in[20];
    const float* wo_g  = (const float*)d_in[21];
    const float* wi0_g = (const float*)d_in[22];
    const float* wi1_g = (const float*)d_in[23];
    const float* wom_g = (const float*)d_in[24];

    float *px, *ph, *pq, *pk, *pv, *patt, *ptmp, *pff, *pff2;
    uint32_t *pwq, *pwk, *pwv, *pwo, *pwi0, *pwi1, *pwom;
    cudaGetSymbolAddress((void**)&px,   g_x);
    cudaGetSymbolAddress((void**)&ph,   g_h);
    cudaGetSymbolAddress((void**)&pq,   g_q);
    cudaGetSymbolAddress((void**)&pk,   g_k);
    cudaGetSymbolAddress((void**)&pv,   g_v);
    cudaGetSymbolAddress((void**)&patt, g_att);
    cudaGetSymbolAddress((void**)&ptmp, g_tmp);
    cudaGetSymbolAddress((void**)&pff,  g_ff);
    cudaGetSymbolAddress((void**)&pff2, g_ff2);
    cudaGetSymbolAddress((void**)&pwq,  g_wq);
    cudaGetSymbolAddress((void**)&pwk,  g_wk);
    cudaGetSymbolAddress((void**)&pwv,  g_wv);
    cudaGetSymbolAddress((void**)&pwo,  g_wo);
    cudaGetSymbolAddress((void**)&pwi0, g_wi0);
    cudaGetSymbolAddress((void**)&pwi1, g_wi1);
    cudaGetSymbolAddress((void**)&pwom, g_wom);

    cudaFuncSetAttribute(attn_kernel, cudaFuncAttributeMaxDynamicSharedMemorySize, ATTN_SMEM_BYTES);
    cudaFuncSetAttribute(tf32_gemm<0>, cudaFuncAttributeMaxDynamicSharedMemorySize, SMEM_GEMM);
    cudaFuncSetAttribute(tf32_gemm<1>, cudaFuncAttributeMaxDynamicSharedMemorySize, SMEM_GEMM);

    int n = MM * DD;
    copy_kernel<<<(n + 255)/256, 256>>>(px, x_in, n);

    run_layer(pre_attn_l, post_attn_l, pre_ffw_l, post_ffw_l,
              wq_l, wk_l, wv_l, wo_l, wi0_l, wi1_l, wom_l,
              pos, seg, /*window=*/1024,
              px, ph, pq, pk, pv, patt, ptmp, pff, pff2,
              pwq, pwk, pwv, pwo, pwi0, pwi1, pwom);

    run_layer(pre_attn_g, post_attn_g, pre_ffw_g, post_ffw_g,
              wq_g, wk_g, wv_g, wo_g, wi0_g, wi1_g, wom_g,
              pos, seg, /*window=*/SS,
              px, ph, pq, pk, pv, patt, ptmp, pff, pff2,
              pwq, pwk, pwv, pwo, pwi0, pwi1, pwom);

    copy_kernel<<<(n + 255)/256, 256>>>((float*)d_out, px, n);
}